// round 2
// baseline (speedup 1.0000x reference)
#include <cuda_runtime.h>
#include <cuda_bf16.h>

#define N_IN   11008
#define N_OUT  4096
#define TOPK_K 5504
#define N_CACHE 64
#define NBW ((N_IN + 31) / 32)   // 344 bitset words

// ---- device-global scratch (allocation-free; rewritten fully each call) ----
__device__ __align__(16) float g_xm[N_IN];
__device__ unsigned char g_mask[N_IN];
__device__ unsigned g_maskbits[NBW];
__device__ int g_inter[N_CACHE];
__device__ int g_use_cache;
__device__ int g_best;

// ============================================================================
// Kernel 1: exact top-K select on |x| via 3-level radix histogram (1 block).
// Produces g_mask (bytes) and g_maskbits (bitset). Ties at the threshold are
// taken in smallest-index order, matching jax.lax.top_k.
// ============================================================================
__global__ void __launch_bounds__(1024) select_kernel(const float* __restrict__ x) {
    __shared__ unsigned hist[2048];
    __shared__ unsigned bits[NBW];
    __shared__ int s_b, s_G;
    __shared__ unsigned s_T;
    __shared__ int s_need;
    __shared__ int scanbuf[32];

    const int tid = threadIdx.x;

    // zero bitset (synced by later __syncthreads)
    for (int i = tid; i < NBW; i += 1024) bits[i] = 0;

    // ---- level 0: bits [30:21] ----
    for (int i = tid; i < 2048; i += 1024) hist[i] = 0;
    __syncthreads();
    for (int i = tid; i < N_IN; i += 1024) {
        unsigned u = __float_as_uint(x[i]) & 0x7FFFFFFFu;
        atomicAdd(&hist[u >> 21], 1u);
    }
    __syncthreads();
    if (tid == 0) {
        int acc = 0, b = 0;
        for (int j = 2047; j >= 0; j--) {
            if (acc + (int)hist[j] >= TOPK_K) { b = j; break; }
            acc += hist[j];
        }
        s_b = b; s_G = acc;
    }
    __syncthreads();
    const int b0 = s_b;

    // ---- level 1: bits [20:10] ----
    for (int i = tid; i < 2048; i += 1024) hist[i] = 0;
    __syncthreads();
    for (int i = tid; i < N_IN; i += 1024) {
        unsigned u = __float_as_uint(x[i]) & 0x7FFFFFFFu;
        if ((int)(u >> 21) == b0) atomicAdd(&hist[(u >> 10) & 0x7FF], 1u);
    }
    __syncthreads();
    if (tid == 0) {
        int acc = s_G, b = 0;
        for (int j = 2047; j >= 0; j--) {
            if (acc + (int)hist[j] >= TOPK_K) { b = j; break; }
            acc += hist[j];
        }
        s_b = b; s_G = acc;
    }
    __syncthreads();
    const int b1 = s_b;

    // ---- level 2: bits [9:0] ----
    for (int i = tid; i < 2048; i += 1024) hist[i] = 0;
    __syncthreads();
    const unsigned top22 = ((unsigned)b0 << 21) | ((unsigned)b1 << 10);
    for (int i = tid; i < N_IN; i += 1024) {
        unsigned u = __float_as_uint(x[i]) & 0x7FFFFFFFu;
        if ((u & 0xFFFFFC00u) == top22) atomicAdd(&hist[u & 0x3FF], 1u);
    }
    __syncthreads();
    if (tid == 0) {
        int acc = s_G, b = 0;
        for (int j = 1023; j >= 0; j--) {
            if (acc + (int)hist[j] >= TOPK_K) { b = j; break; }
            acc += hist[j];
        }
        s_T = top22 | (unsigned)b;
        s_need = TOPK_K - acc;   // how many threshold-equal elements to take
    }
    __syncthreads();
    const unsigned T = s_T;
    const int need = s_need;

    // ---- mask build with smallest-index tie-break ----
    const int CHUNK = (N_IN + 1023) / 1024;   // 11
    const int start = tid * CHUNK;
    const int end   = min(start + CHUNK, N_IN);

    int tieCnt = 0;
    for (int i = start; i < end; i++) {
        unsigned u = __float_as_uint(x[i]) & 0x7FFFFFFFu;
        if (u == T) tieCnt++;
    }
    // block exclusive scan of tieCnt (1024 threads)
    const int lane = tid & 31, wid = tid >> 5;
    int v = tieCnt;
    #pragma unroll
    for (int o = 1; o < 32; o <<= 1) {
        int t = __shfl_up_sync(0xffffffffu, v, o);
        if (lane >= o) v += t;
    }
    if (lane == 31) scanbuf[wid] = v;
    __syncthreads();
    if (wid == 0) {
        int w = scanbuf[lane];
        #pragma unroll
        for (int o = 1; o < 32; o <<= 1) {
            int t = __shfl_up_sync(0xffffffffu, w, o);
            if (lane >= o) w += t;
        }
        scanbuf[lane] = w;
    }
    __syncthreads();
    int tieRank = (v - tieCnt) + (wid > 0 ? scanbuf[wid - 1] : 0);

    for (int i = start; i < end; i++) {
        unsigned u = __float_as_uint(x[i]) & 0x7FFFFFFFu;
        int sel;
        if (u > T)       sel = 1;
        else if (u == T) { sel = (tieRank < need); tieRank++; }
        else             sel = 0;
        g_mask[i] = (unsigned char)sel;
        if (sel) atomicOr(&bits[i >> 5], 1u << (i & 31));
    }
    __syncthreads();
    for (int i = tid; i < NBW; i += 1024) g_maskbits[i] = bits[i];
}

// ============================================================================
// Kernel 2: per-cache DEDUPED intersection with topk mask (bitset popc).
// cached_indices are int32 (JAX default x64-disabled downcasts int64->int32).
// ============================================================================
__global__ void __launch_bounds__(256) recall_kernel(const int* __restrict__ cached) {
    __shared__ unsigned cbits[NBW];
    __shared__ int wsum[8];
    const int b = blockIdx.x, tid = threadIdx.x;

    for (int i = tid; i < NBW; i += 256) cbits[i] = 0;
    __syncthreads();

    const int* row = cached + (long long)b * TOPK_K;
    for (int k = tid; k < TOPK_K; k += 256) {
        int idx = row[k];
        atomicOr(&cbits[idx >> 5], 1u << (idx & 31));
    }
    __syncthreads();

    int cnt = 0;
    for (int i = tid; i < NBW; i += 256) cnt += __popc(cbits[i] & g_maskbits[i]);
    #pragma unroll
    for (int o = 16; o; o >>= 1) cnt += __shfl_down_sync(0xffffffffu, cnt, o);
    if ((tid & 31) == 0) wsum[tid >> 5] = cnt;
    __syncthreads();
    if (tid == 0) {
        int s = 0;
        #pragma unroll
        for (int i = 0; i < 8; i++) s += wsum[i];
        g_inter[b] = s;
    }
}

// ============================================================================
// Kernel 3: argmax (first-max) + threshold decision, mirroring the reference.
// ============================================================================
__global__ void decide_kernel() {
    float best = -1.0f;
    int bi = 0;
    for (int i = 0; i < N_CACHE; i++) {
        float r = (float)g_inter[i] / (float)TOPK_K;
        if (r > best) { best = r; bi = i; }
    }
    g_best = bi;
    g_use_cache = (best >= 0.9f) ? 1 : 0;
}

// ============================================================================
// Kernel 4a: masked x for the top-k path (zeros if cache path chosen).
// Kernel 4b: multiplicity scatter-add for the cache path.
// ============================================================================
__global__ void build_xm_kernel(const float* __restrict__ x) {
    int i = blockIdx.x * blockDim.x + threadIdx.x;
    if (i < N_IN)
        g_xm[i] = (!g_use_cache && g_mask[i]) ? x[i] : 0.0f;
}

__global__ void scatter_xm_kernel(const float* __restrict__ x,
                                  const int* __restrict__ cached) {
    if (!g_use_cache) return;
    int k = blockIdx.x * blockDim.x + threadIdx.x;
    if (k < TOPK_K) {
        int idx = cached[(long long)g_best * TOPK_K + k];
        atomicAdd(&g_xm[idx], x[idx]);   // duplicates = multiplicity
    }
}

// ============================================================================
// Kernel 5: dense GEMV  out = W @ xm + bias.  180 MB of W — the HBM roofline.
// One row per block, float4 vectorized, warp+block reduce.
// ============================================================================
__global__ void __launch_bounds__(256) gemv_kernel(const float* __restrict__ W,
                                                   const float* __restrict__ bias,
                                                   float* __restrict__ out) {
    const int row = blockIdx.x;
    const float4* __restrict__ w4 = (const float4*)(W + (long long)row * N_IN);
    const float4* __restrict__ x4 = (const float4*)g_xm;

    float acc = 0.0f;
    #pragma unroll 4
    for (int j = threadIdx.x; j < N_IN / 4; j += 256) {
        float4 w = w4[j];
        float4 v = x4[j];
        acc += w.x * v.x + w.y * v.y + w.z * v.z + w.w * v.w;
    }
    #pragma unroll
    for (int o = 16; o; o >>= 1) acc += __shfl_down_sync(0xffffffffu, acc, o);

    __shared__ float ws[8];
    const int lane = threadIdx.x & 31, wid = threadIdx.x >> 5;
    if (lane == 0) ws[wid] = acc;
    __syncthreads();
    if (threadIdx.x == 0) {
        float s = 0.0f;
        #pragma unroll
        for (int i = 0; i < 8; i++) s += ws[i];
        out[row] = s + bias[row];
    }
}

// ============================================================================
extern "C" void kernel_launch(void* const* d_in, const int* in_sizes, int n_in,
                              void* d_out, int out_size) {
    const float* x      = (const float*)d_in[0];
    const float* W      = (const float*)d_in[1];
    const float* bias   = (const float*)d_in[2];
    const int*   cached = (const int*)d_in[3];
    float*       out    = (float*)d_out;

    select_kernel<<<1, 1024>>>(x);
    recall_kernel<<<N_CACHE, 256>>>(cached);
    decide_kernel<<<1, 1>>>();
    build_xm_kernel<<<(N_IN + 255) / 256, 256>>>(x);
    scatter_xm_kernel<<<(TOPK_K + 255) / 256, 256>>>(x, cached);
    gemv_kernel<<<N_OUT, 256>>>(W, bias, out);
}

// round 3
// speedup vs baseline: 2.1201x; 2.1201x over previous
#include <cuda_runtime.h>
#include <cuda_bf16.h>

#define N_IN   11008
#define N_OUT  4096
#define TOPK_K 5504
#define N_CACHE 64
#define NBW ((N_IN + 31) / 32)   // 344 bitset words

// ---- device-global scratch (allocation-free; rewritten fully each call) ----
__device__ __align__(16) float g_xm[N_IN];
__device__ unsigned char g_mask[N_IN];
__device__ unsigned g_maskbits[NBW];
__device__ int g_inter[N_CACHE];
__device__ int g_use_cache;
__device__ int g_best;

// Block-wide inclusive scan over 1024 threads (one int each).
__device__ __forceinline__ int block_incl_scan(int v, int lane, int wid, int* sbuf) {
    __syncthreads();                       // protect sbuf from previous use
    #pragma unroll
    for (int o = 1; o < 32; o <<= 1) {
        int t = __shfl_up_sync(0xffffffffu, v, o);
        if (lane >= o) v += t;
    }
    if (lane == 31) sbuf[wid] = v;
    __syncthreads();
    if (wid == 0) {
        int w = sbuf[lane];
        #pragma unroll
        for (int o = 1; o < 32; o <<= 1) {
            int t = __shfl_up_sync(0xffffffffu, w, o);
            if (lane >= o) w += t;
        }
        sbuf[lane] = w;
    }
    __syncthreads();
    if (wid > 0) v += sbuf[wid - 1];
    return v;
}

// ============================================================================
// Kernel 1: exact top-K on |x| via 3-level radix histogram, fully parallel
// bucket search (suffix sums via block scan). Smallest-index tie-break.
// ============================================================================
__global__ void __launch_bounds__(1024) select_kernel(const float* __restrict__ x) {
    __shared__ unsigned hist[2048];
    __shared__ unsigned bits[NBW];
    __shared__ int s_b, s_G;
    __shared__ unsigned s_T;
    __shared__ int s_need;
    __shared__ int scanbuf[32];

    const int tid  = threadIdx.x;
    const int lane = tid & 31, wid = tid >> 5;

    for (int i = tid; i < NBW; i += 1024) bits[i] = 0;

    // ---------------- level 0: bits [30:21], 2048 bins ----------------
    for (int i = tid; i < 2048; i += 1024) hist[i] = 0;
    __syncthreads();
    for (int i = tid; i < N_IN; i += 1024) {
        unsigned u = __float_as_uint(x[i]) & 0x7FFFFFFFu;
        atomicAdd(&hist[u >> 21], 1u);
    }
    __syncthreads();
    {
        const int j0 = 2047 - 2 * tid;       // larger bin of this thread's pair
        const int j1 = j0 - 1;
        const int h0 = hist[j0], h1 = hist[j1];
        int S = block_incl_scan(h0 + h1, lane, wid, scanbuf);  // cnt_ge[j1]
        int excl = S - h0 - h1;                                 // cnt_ge[j0+1]
        const int Kr = TOPK_K;
        if (excl + h0 >= Kr && excl < Kr)      { s_b = j0; s_G = excl; }
        else if (S >= Kr && excl + h0 < Kr)    { s_b = j1; s_G = excl + h0; }
    }
    __syncthreads();
    const int b0 = s_b;
    const int G0 = s_G;

    // ---------------- level 1: bits [20:10], 2048 bins ----------------
    __syncthreads();
    for (int i = tid; i < 2048; i += 1024) hist[i] = 0;
    __syncthreads();
    for (int i = tid; i < N_IN; i += 1024) {
        unsigned u = __float_as_uint(x[i]) & 0x7FFFFFFFu;
        if ((int)(u >> 21) == b0) atomicAdd(&hist[(u >> 10) & 0x7FF], 1u);
    }
    __syncthreads();
    {
        const int j0 = 2047 - 2 * tid;
        const int j1 = j0 - 1;
        const int h0 = hist[j0], h1 = hist[j1];
        int S = block_incl_scan(h0 + h1, lane, wid, scanbuf);
        int excl = S - h0 - h1;
        const int Kr = TOPK_K - G0;
        if (excl + h0 >= Kr && excl < Kr)      { s_b = j0; s_G = G0 + excl; }
        else if (S >= Kr && excl + h0 < Kr)    { s_b = j1; s_G = G0 + excl + h0; }
    }
    __syncthreads();
    const int b1 = s_b;
    const int G1 = s_G;

    // ---------------- level 2: bits [9:0], 1024 bins ----------------
    __syncthreads();
    for (int i = tid; i < 2048; i += 1024) hist[i] = 0;
    __syncthreads();
    const unsigned top22 = ((unsigned)b0 << 21) | ((unsigned)b1 << 10);
    for (int i = tid; i < N_IN; i += 1024) {
        unsigned u = __float_as_uint(x[i]) & 0x7FFFFFFFu;
        if ((u & 0xFFFFFC00u) == top22) atomicAdd(&hist[u & 0x3FF], 1u);
    }
    __syncthreads();
    {
        const int j = 1023 - tid;
        const int h = hist[j];
        int S = block_incl_scan(h, lane, wid, scanbuf);   // cnt_ge[j]
        int excl = S - h;                                  // cnt_ge[j+1]
        const int Kr = TOPK_K - G1;
        if (S >= Kr && excl < Kr) {
            s_T = top22 | (unsigned)j;
            s_need = Kr - excl;
        }
    }
    __syncthreads();
    const unsigned T = s_T;
    const int need = s_need;

    // ---- mask build with smallest-index tie-break ----
    const int CHUNK = (N_IN + 1023) / 1024;   // 11
    const int start = tid * CHUNK;
    const int end   = min(start + CHUNK, N_IN);

    int tieCnt = 0;
    for (int i = start; i < end; i++) {
        unsigned u = __float_as_uint(x[i]) & 0x7FFFFFFFu;
        if (u == T) tieCnt++;
    }
    int incl = block_incl_scan(tieCnt, lane, wid, scanbuf);
    int tieRank = incl - tieCnt;

    for (int i = start; i < end; i++) {
        unsigned u = __float_as_uint(x[i]) & 0x7FFFFFFFu;
        int sel;
        if (u > T)       sel = 1;
        else if (u == T) { sel = (tieRank < need); tieRank++; }
        else             sel = 0;
        g_mask[i] = (unsigned char)sel;
        if (sel) atomicOr(&bits[i >> 5], 1u << (i & 31));
    }
    __syncthreads();
    for (int i = tid; i < NBW; i += 1024) g_maskbits[i] = bits[i];
}

// ============================================================================
// Kernel 2: per-cache DEDUPED intersection with topk mask (bitset popc).
// cached_indices arrive as int32.
// ============================================================================
__global__ void __launch_bounds__(256) recall_kernel(const int* __restrict__ cached) {
    __shared__ unsigned cbits[NBW];
    __shared__ int wsum[8];
    const int b = blockIdx.x, tid = threadIdx.x;

    for (int i = tid; i < NBW; i += 256) cbits[i] = 0;
    __syncthreads();

    const int* row = cached + (long long)b * TOPK_K;
    for (int k = tid; k < TOPK_K; k += 256) {
        int idx = row[k];
        atomicOr(&cbits[idx >> 5], 1u << (idx & 31));
    }
    __syncthreads();

    int cnt = 0;
    for (int i = tid; i < NBW; i += 256) cnt += __popc(cbits[i] & g_maskbits[i]);
    #pragma unroll
    for (int o = 16; o; o >>= 1) cnt += __shfl_down_sync(0xffffffffu, cnt, o);
    if ((tid & 31) == 0) wsum[tid >> 5] = cnt;
    __syncthreads();
    if (tid == 0) {
        int s = 0;
        #pragma unroll
        for (int i = 0; i < 8; i++) s += wsum[i];
        g_inter[b] = s;
    }
}

// ============================================================================
// Kernel 3: masked x build with decision fused (argmax over 64 recalls is
// recomputed per block by thread 0 — cheap, removes a launch).
// ============================================================================
__global__ void build_xm_kernel(const float* __restrict__ x) {
    __shared__ int s_use;
    if (threadIdx.x == 0) {
        float best = -1.0f; int bi = 0;
        #pragma unroll
        for (int i = 0; i < N_CACHE; i++) {
            float r = (float)g_inter[i] / (float)TOPK_K;
            if (r > best) { best = r; bi = i; }
        }
        int use = (best >= 0.9f) ? 1 : 0;
        s_use = use;
        if (blockIdx.x == 0) { g_best = bi; g_use_cache = use; }
    }
    __syncthreads();
    int i = blockIdx.x * blockDim.x + threadIdx.x;
    if (i < N_IN)
        g_xm[i] = (!s_use && g_mask[i]) ? x[i] : 0.0f;
}

// ============================================================================
// Kernel 4: multiplicity scatter-add for the cache path (no-op otherwise).
// ============================================================================
__global__ void scatter_xm_kernel(const float* __restrict__ x,
                                  const int* __restrict__ cached) {
    if (!g_use_cache) return;
    int k = blockIdx.x * blockDim.x + threadIdx.x;
    if (k < TOPK_K) {
        int idx = cached[(long long)g_best * TOPK_K + k];
        atomicAdd(&g_xm[idx], x[idx]);   // duplicates = multiplicity
    }
}

// ============================================================================
// Kernel 5: dense GEMV  out = W @ xm + bias.  Warp-per-row: no block reduce,
// 86 float4 loads/lane, two accumulators. 180 MB of W = the HBM roofline.
// ============================================================================
__global__ void __launch_bounds__(256) gemv_kernel(const float* __restrict__ W,
                                                   const float* __restrict__ bias,
                                                   float* __restrict__ out) {
    const int row  = (blockIdx.x * 256 + threadIdx.x) >> 5;
    const int lane = threadIdx.x & 31;

    const float4* __restrict__ w4 = (const float4*)(W + (long long)row * N_IN);
    const float4* __restrict__ x4 = (const float4*)g_xm;

    float a0 = 0.0f, a1 = 0.0f;
    // N_IN/4 = 2752 = 43 * 64 exactly: two float4 per lane per iteration.
    #pragma unroll 4
    for (int it = 0; it < 43; it++) {
        const int j = lane + it * 64;
        float4 w = w4[j];
        float4 v = x4[j];
        a0 += w.x * v.x + w.y * v.y;
        a1 += w.z * v.z + w.w * v.w;
        float4 w2 = w4[j + 32];
        float4 v2 = x4[j + 32];
        a0 += w2.x * v2.x + w2.y * v2.y;
        a1 += w2.z * v2.z + w2.w * v2.w;
    }
    float acc = a0 + a1;
    #pragma unroll
    for (int o = 16; o; o >>= 1) acc += __shfl_down_sync(0xffffffffu, acc, o);
    if (lane == 0) out[row] = acc + bias[row];
}

// ============================================================================
extern "C" void kernel_launch(void* const* d_in, const int* in_sizes, int n_in,
                              void* d_out, int out_size) {
    const float* x      = (const float*)d_in[0];
    const float* W      = (const float*)d_in[1];
    const float* bias   = (const float*)d_in[2];
    const int*   cached = (const int*)d_in[3];
    float*       out    = (float*)d_out;

    select_kernel<<<1, 1024>>>(x);
    recall_kernel<<<N_CACHE, 256>>>(cached);
    build_xm_kernel<<<(N_IN + 255) / 256, 256>>>(x);
    scatter_xm_kernel<<<(TOPK_K + 255) / 256, 256>>>(x, cached);
    gemv_kernel<<<(N_OUT * 32) / 256, 256>>>(W, bias, out);
}

// round 4
// speedup vs baseline: 2.5136x; 1.1856x over previous
#include <cuda_runtime.h>
#include <cuda_bf16.h>

#define N_IN   11008
#define N_OUT  4096
#define TOPK_K 5504
#define N_CACHE 64
#define NBW ((N_IN + 31) / 32)   // 344 bitset words
#define NBLK 64                  // fused kernel grid size

// ---- device-global scratch (allocation-free) ----
__device__ __align__(16) float g_xm[N_IN];
__device__ unsigned g_maskbits[NBW];
__device__ int g_inter[N_CACHE];
__device__ unsigned g_barcnt;    // monotonic grid-barrier counter (replay-safe)

// ============================================================================
// Replay-safe grid barrier: monotonic counter, generation = count / NBLK.
// Launches are stream-serialized, so at each barrier instance the counter is
// an exact multiple of NBLK; every arrival computes the same target.
// ============================================================================
__device__ __forceinline__ void grid_barrier() {
    __syncthreads();
    if (threadIdx.x == 0) {
        __threadfence();                                  // publish my writes
        unsigned old = atomicAdd(&g_barcnt, 1u);
        unsigned target = (old / NBLK + 1u) * NBLK;
        unsigned cur;
        do {
            asm volatile("ld.acquire.gpu.u32 %0, [%1];"
                         : "=r"(cur) : "l"(&g_barcnt) : "memory");
        } while (cur < target);
    }
    __syncthreads();
}

// Block-wide inclusive scan over 1024 threads (one int each).
__device__ __forceinline__ int block_incl_scan(int v, int lane, int wid, int* sbuf) {
    __syncthreads();
    #pragma unroll
    for (int o = 1; o < 32; o <<= 1) {
        int t = __shfl_up_sync(0xffffffffu, v, o);
        if (lane >= o) v += t;
    }
    if (lane == 31) sbuf[wid] = v;
    __syncthreads();
    if (wid == 0) {
        int w = sbuf[lane];
        #pragma unroll
        for (int o = 1; o < 32; o <<= 1) {
            int t = __shfl_up_sync(0xffffffffu, w, o);
            if (lane >= o) w += t;
        }
        sbuf[lane] = w;
    }
    __syncthreads();
    if (wid > 0) v += sbuf[wid - 1];
    return v;
}

// Top-K select on |x|, 3-level radix histogram, executed by block 0 only.
// Writes g_maskbits. Smallest-index tie-break (matches jax.lax.top_k).
__device__ void do_select(const float* __restrict__ x,
                          unsigned* hist, unsigned* bits, int* scanbuf,
                          int* s_b, int* s_G, unsigned* s_T, int* s_need) {
    const int tid  = threadIdx.x;
    const int lane = tid & 31, wid = tid >> 5;

    for (int i = tid; i < NBW; i += 1024) bits[i] = 0;

    // ---- level 0: bits [30:21] ----
    for (int i = tid; i < 2048; i += 1024) hist[i] = 0;
    __syncthreads();
    for (int i = tid; i < N_IN; i += 1024) {
        unsigned u = __float_as_uint(x[i]) & 0x7FFFFFFFu;
        atomicAdd(&hist[u >> 21], 1u);
    }
    __syncthreads();
    {
        const int j0 = 2047 - 2 * tid, j1 = j0 - 1;
        const int h0 = hist[j0], h1 = hist[j1];
        int S = block_incl_scan(h0 + h1, lane, wid, scanbuf);
        int excl = S - h0 - h1;
        const int Kr = TOPK_K;
        if (excl + h0 >= Kr && excl < Kr)   { *s_b = j0; *s_G = excl; }
        else if (S >= Kr && excl + h0 < Kr) { *s_b = j1; *s_G = excl + h0; }
    }
    __syncthreads();
    const int b0 = *s_b, G0 = *s_G;

    // ---- level 1: bits [20:10] ----
    __syncthreads();
    for (int i = tid; i < 2048; i += 1024) hist[i] = 0;
    __syncthreads();
    for (int i = tid; i < N_IN; i += 1024) {
        unsigned u = __float_as_uint(x[i]) & 0x7FFFFFFFu;
        if ((int)(u >> 21) == b0) atomicAdd(&hist[(u >> 10) & 0x7FF], 1u);
    }
    __syncthreads();
    {
        const int j0 = 2047 - 2 * tid, j1 = j0 - 1;
        const int h0 = hist[j0], h1 = hist[j1];
        int S = block_incl_scan(h0 + h1, lane, wid, scanbuf);
        int excl = S - h0 - h1;
        const int Kr = TOPK_K - G0;
        if (excl + h0 >= Kr && excl < Kr)   { *s_b = j0; *s_G = G0 + excl; }
        else if (S >= Kr && excl + h0 < Kr) { *s_b = j1; *s_G = G0 + excl + h0; }
    }
    __syncthreads();
    const int b1 = *s_b, G1 = *s_G;

    // ---- level 2: bits [9:0] ----
    __syncthreads();
    for (int i = tid; i < 2048; i += 1024) hist[i] = 0;
    __syncthreads();
    const unsigned top22 = ((unsigned)b0 << 21) | ((unsigned)b1 << 10);
    for (int i = tid; i < N_IN; i += 1024) {
        unsigned u = __float_as_uint(x[i]) & 0x7FFFFFFFu;
        if ((u & 0xFFFFFC00u) == top22) atomicAdd(&hist[u & 0x3FF], 1u);
    }
    __syncthreads();
    {
        const int j = 1023 - tid;
        const int h = hist[j];
        int S = block_incl_scan(h, lane, wid, scanbuf);
        int excl = S - h;
        const int Kr = TOPK_K - G1;
        if (S >= Kr && excl < Kr) { *s_T = top22 | (unsigned)j; *s_need = Kr - excl; }
    }
    __syncthreads();
    const unsigned T = *s_T;
    const int need = *s_need;

    // ---- mask build with smallest-index tie-break ----
    const int CHUNK = (N_IN + 1023) / 1024;   // 11
    const int start = tid * CHUNK;
    const int end   = min(start + CHUNK, N_IN);

    int tieCnt = 0;
    for (int i = start; i < end; i++) {
        unsigned u = __float_as_uint(x[i]) & 0x7FFFFFFFu;
        if (u == T) tieCnt++;
    }
    int incl = block_incl_scan(tieCnt, lane, wid, scanbuf);
    int tieRank = incl - tieCnt;

    for (int i = start; i < end; i++) {
        unsigned u = __float_as_uint(x[i]) & 0x7FFFFFFFu;
        int sel;
        if (u > T)       sel = 1;
        else if (u == T) { sel = (tieRank < need); tieRank++; }
        else             sel = 0;
        if (sel) atomicOr(&bits[i >> 5], 1u << (i & 31));
    }
    __syncthreads();
    for (int i = tid; i < NBW; i += 1024) g_maskbits[i] = bits[i];
}

// ============================================================================
// Fused kernel: recall bitsets + top-K select (block 0) | popc | decide + xm.
// 64 blocks x 1024 threads, all co-resident; grid barriers between phases.
// ============================================================================
__global__ void __launch_bounds__(1024) fused_kernel(const float* __restrict__ x,
                                                     const int* __restrict__ cached) {
    __shared__ unsigned cbits[NBW];
    __shared__ unsigned hist[2048];
    __shared__ unsigned bits[NBW];
    __shared__ int scanbuf[32];
    __shared__ int wsum[32];
    __shared__ int s_b, s_G, s_need, s_use, s_best;
    __shared__ unsigned s_T;

    const int b = blockIdx.x, tid = threadIdx.x;
    const int lane = tid & 31, wid = tid >> 5;

    // ---- Phase 0: dedup bitset for cache b ----
    for (int i = tid; i < NBW; i += 1024) cbits[i] = 0;
    __syncthreads();
    {
        const int* row = cached + b * TOPK_K;
        for (int k = tid; k < TOPK_K; k += 1024) {
            int idx = row[k];
            atomicOr(&cbits[idx >> 5], 1u << (idx & 31));
        }
    }

    // ---- Phase 0b: block 0 runs top-K select (others proceed to barrier) ----
    if (b == 0)
        do_select(x, hist, bits, scanbuf, &s_b, &s_G, &s_T, &s_need);

    grid_barrier();   // g_maskbits published

    // ---- Phase 1: deduped intersection count ----
    int cnt = 0;
    for (int i = tid; i < NBW; i += 1024) cnt += __popc(cbits[i] & g_maskbits[i]);
    #pragma unroll
    for (int o = 16; o; o >>= 1) cnt += __shfl_down_sync(0xffffffffu, cnt, o);
    if (lane == 0) wsum[wid] = cnt;
    __syncthreads();
    if (tid == 0) {
        int s = 0;
        #pragma unroll
        for (int i = 0; i < 32; i++) s += wsum[i];
        g_inter[b] = s;
    }

    grid_barrier();   // g_inter published

    // ---- Phase 2: decision (redundant per block) + xm slice build ----
    if (tid == 0) {
        float best = -1.0f; int bi = 0;
        #pragma unroll
        for (int i = 0; i < N_CACHE; i++) {
            float r = (float)g_inter[i] / (float)TOPK_K;
            if (r > best) { best = r; bi = i; }   // first-max = argmax
        }
        s_use  = (best >= 0.9f) ? 1 : 0;
        s_best = bi;
    }
    __syncthreads();

    const int base = b * (N_IN / NBLK);     // 172 per block
    if (!s_use) {
        for (int i = base + tid; i < base + N_IN / NBLK; i += 1024) {
            int sel = (g_maskbits[i >> 5] >> (i & 31)) & 1;
            g_xm[i] = sel ? x[i] : 0.0f;
        }
    } else {
        for (int i = base + tid; i < base + N_IN / NBLK; i += 1024)
            g_xm[i] = 0.0f;
        grid_barrier();                      // all of xm zeroed
        const int kbase = b * (TOPK_K / NBLK);   // 86 per block
        const int* brow = cached + s_best * TOPK_K;
        for (int k = kbase + tid; k < kbase + TOPK_K / NBLK; k += 1024) {
            int idx = brow[k];
            atomicAdd(&g_xm[idx], x[idx]);   // duplicates = multiplicity
        }
    }
}

// ============================================================================
// GEMV: out = W @ xm + bias. Warp-per-row, float4, streaming hint on W.
// 180 MB of W reads = the HBM roofline (~29 us floor).
// ============================================================================
__global__ void __launch_bounds__(256) gemv_kernel(const float* __restrict__ W,
                                                   const float* __restrict__ bias,
                                                   float* __restrict__ out) {
    const int row  = (blockIdx.x * 256 + threadIdx.x) >> 5;
    const int lane = threadIdx.x & 31;

    const float4* __restrict__ w4 = (const float4*)(W + (long long)row * N_IN);
    const float4* __restrict__ x4 = (const float4*)g_xm;

    float a0 = 0.0f, a1 = 0.0f;
    // N_IN/4 = 2752 = 43 * 64: two float4 per lane per iteration.
    #pragma unroll 4
    for (int it = 0; it < 43; it++) {
        const int j = lane + it * 64;
        float4 w  = __ldcs(w4 + j);
        float4 v  = x4[j];
        a0 += w.x * v.x + w.y * v.y;
        a1 += w.z * v.z + w.w * v.w;
        float4 w2 = __ldcs(w4 + j + 32);
        float4 v2 = x4[j + 32];
        a0 += w2.x * v2.x + w2.y * v2.y;
        a1 += w2.z * v2.z + w2.w * v2.w;
    }
    float acc = a0 + a1;
    #pragma unroll
    for (int o = 16; o; o >>= 1) acc += __shfl_down_sync(0xffffffffu, acc, o);
    if (lane == 0) out[row] = acc + bias[row];
}

// ============================================================================
extern "C" void kernel_launch(void* const* d_in, const int* in_sizes, int n_in,
                              void* d_out, int out_size) {
    const float* x      = (const float*)d_in[0];
    const float* W      = (const float*)d_in[1];
    const float* bias   = (const float*)d_in[2];
    const int*   cached = (const int*)d_in[3];
    float*       out    = (float*)d_out;

    fused_kernel<<<NBLK, 1024>>>(x, cached);
    gemv_kernel<<<(N_OUT * 32) / 256, 256>>>(W, bias, out);
}